// round 16
// baseline (speedup 1.0000x reference)
#include <cuda_runtime.h>
#include <cuda_fp16.h>
#include <cstdint>

// out[b, :] = (1/K) * sum_k table[idx[b,k], :],  V=200000 D=128 B=50000 K=32.
//
// Pass 1: f32 table -> fp16 scratch (51.2MB; evict_last stores keep it mostly
//         L2-resident). Streaming at the HBM cap. 4 float4 per thread.
// Pass 2: fp16 gather (R15 structure: warp/row, LDG.64/lane, batch-4 full
//         unroll, depth-2 __hadd2 pre-reduction, regs 32). 256-thr CTAs to
//         cut CTA churn (R15 achieved occ 88% at 128-thr).

static constexpr long long MAX_VD4 = 6400000;   // 200000*128/4 uint2 slots
__device__ uint2 g_tab16[MAX_VD4];              // fp16 table: 51.2 MB scratch

__device__ __forceinline__ unsigned long long make_policy_el() {
    unsigned long long pol;
    asm("createpolicy.fractional.L2::evict_last.b64 %0, 1.0;" : "=l"(pol));
    return pol;
}

// ---------------- pass 1: f32 -> f16 convert (streaming) ----------------
__global__ __launch_bounds__(256) void convert_f32_to_f16(
    const float4* __restrict__ in, long long n16)  // n16 = groups of 4 float4
{
    long long i = (long long)blockIdx.x * blockDim.x + threadIdx.x;
    if (i >= n16) return;
    const unsigned long long pol = make_policy_el();

    float4 a = __ldcs(&in[4 * i]);
    float4 b = __ldcs(&in[4 * i + 1]);
    float4 c = __ldcs(&in[4 * i + 2]);
    float4 d = __ldcs(&in[4 * i + 3]);

    __half2 h0 = __floats2half2_rn(a.x, a.y);
    __half2 h1 = __floats2half2_rn(a.z, a.w);
    __half2 h2 = __floats2half2_rn(b.x, b.y);
    __half2 h3 = __floats2half2_rn(b.z, b.w);
    __half2 h4 = __floats2half2_rn(c.x, c.y);
    __half2 h5 = __floats2half2_rn(c.z, c.w);
    __half2 h6 = __floats2half2_rn(d.x, d.y);
    __half2 h7 = __floats2half2_rn(d.z, d.w);

    unsigned u0 = *reinterpret_cast<unsigned*>(&h0);
    unsigned u1 = *reinterpret_cast<unsigned*>(&h1);
    unsigned u2 = *reinterpret_cast<unsigned*>(&h2);
    unsigned u3 = *reinterpret_cast<unsigned*>(&h3);
    unsigned u4 = *reinterpret_cast<unsigned*>(&h4);
    unsigned u5 = *reinterpret_cast<unsigned*>(&h5);
    unsigned u6 = *reinterpret_cast<unsigned*>(&h6);
    unsigned u7 = *reinterpret_cast<unsigned*>(&h7);

    asm volatile("st.global.L2::cache_hint.v4.b32 [%0], {%1,%2,%3,%4}, %5;"
                 :: "l"(&g_tab16[4 * i]), "r"(u0), "r"(u1), "r"(u2), "r"(u3),
                    "l"(pol));
    asm volatile("st.global.L2::cache_hint.v4.b32 [%0], {%1,%2,%3,%4}, %5;"
                 :: "l"(&g_tab16[4 * i + 2]), "r"(u4), "r"(u5), "r"(u6), "r"(u7),
                    "l"(pol));
}

// ---------------- pass 2: fp16 gather ----------------
__device__ __forceinline__ uint2 ldg64_pol(const char* p, unsigned long long pol) {
    uint2 v;
    asm volatile("ld.global.nc.L2::cache_hint.v2.b32 {%0,%1}, [%2], %3;"
                 : "=r"(v.x), "=r"(v.y) : "l"(p), "l"(pol));
    return v;
}

__global__ __launch_bounds__(256) void gather_mean_f16_k32(
    const int* __restrict__ idx,
    float4* __restrict__ out,
    int B)
{
    const int warp = (blockIdx.x * blockDim.x + threadIdx.x) >> 5;
    const int lane = threadIdx.x & 31;
    if (warp >= B) return;

    const unsigned long long pol = make_policy_el();
    const char* tab = (const char*)g_tab16;     // byte base; offsets fit in u32

    // coalesced 128B streaming load of this row's 32 indices
    int my_idx = __ldcs(&idx[(long long)warp * 32 + lane]);

    const unsigned laneOfs = (unsigned)lane * 8u;

    float ax = 0.f, ay = 0.f, az = 0.f, aw = 0.f;

#pragma unroll
    for (int kb = 0; kb < 32; kb += 4) {
        uint2 v[4];
#pragma unroll
        for (int j = 0; j < 4; ++j) {
            int n = __shfl_sync(0xffffffffu, my_idx, kb + j);
            unsigned ofs = (unsigned)n * 256u + laneOfs;   // fp16 row = 256B
            v[j] = ldg64_pol(tab + ofs, pol);
        }
        // depth-2 fp16 pre-reduction: combine 4 rows before conversion
        __half2 p0 = __hadd2(*reinterpret_cast<__half2*>(&v[0].x),
                             *reinterpret_cast<__half2*>(&v[1].x));
        __half2 q0 = __hadd2(*reinterpret_cast<__half2*>(&v[2].x),
                             *reinterpret_cast<__half2*>(&v[3].x));
        __half2 p1 = __hadd2(*reinterpret_cast<__half2*>(&v[0].y),
                             *reinterpret_cast<__half2*>(&v[1].y));
        __half2 q1 = __hadd2(*reinterpret_cast<__half2*>(&v[2].y),
                             *reinterpret_cast<__half2*>(&v[3].y));
        __half2 s0 = __hadd2(p0, q0);
        __half2 s1 = __hadd2(p1, q1);
        float2 f0 = __half22float2(s0);
        float2 f1 = __half22float2(s1);
        ax += f0.x; ay += f0.y;
        az += f1.x; aw += f1.y;
    }

    const float inv = 1.0f / 32.0f;
    float4 r;
    r.x = ax * inv; r.y = ay * inv; r.z = az * inv; r.w = aw * inv;
    __stcs(&out[(long long)warp * 32 + lane], r);
}

// ---------------- fallback: f32 path (K != 32 or oversized table) --------
__global__ __launch_bounds__(256) void gather_mean_generic(
    const float4* __restrict__ table,
    const int* __restrict__ idx,
    float4* __restrict__ out,
    int B, int K)
{
    const int warp = (blockIdx.x * blockDim.x + threadIdx.x) >> 5;
    const int lane = threadIdx.x & 31;
    if (warp >= B) return;

    const int* row_idx = idx + (long long)warp * K;

    float4 acc = make_float4(0.f, 0.f, 0.f, 0.f);
    int k = 0;
    for (; k + 8 <= K; k += 8) {
        float4 v[8];
#pragma unroll
        for (int j = 0; j < 8; ++j) {
            int n = __ldg(&row_idx[k + j]);
            v[j] = __ldg(&table[(long long)n * 32 + lane]);
        }
#pragma unroll
        for (int j = 0; j < 8; ++j) {
            acc.x += v[j].x; acc.y += v[j].y;
            acc.z += v[j].z; acc.w += v[j].w;
        }
    }
    for (; k < K; ++k) {
        int n = row_idx[k];
        float4 v = __ldg(&table[(long long)n * 32 + lane]);
        acc.x += v.x; acc.y += v.y; acc.z += v.z; acc.w += v.w;
    }

    const float inv = 1.0f / (float)K;
    acc.x *= inv; acc.y *= inv; acc.z *= inv; acc.w *= inv;
    out[(long long)warp * 32 + lane] = acc;
}

extern "C" void kernel_launch(void* const* d_in, const int* in_sizes, int n_in,
                              void* d_out, int out_size)
{
    const int B = out_size / 128;                   // rows of output
    const int K = (B > 0) ? (in_sizes[1] / B) : 0;
    const long long VD = (long long)in_sizes[0];    // table element count

    if (K == 32 && VD % 16 == 0 && VD / 4 <= MAX_VD4 && (VD & 127) == 0) {
        const float4* table = (const float4*)d_in[0];
        const int*    idx   = (const int*)d_in[1];
        float4*       out   = (float4*)d_out;

        const long long n16 = VD / 16;              // 4 float4 per thread
        const int cblocks = (int)((n16 + 255) / 256);
        convert_f32_to_f16<<<cblocks, 256>>>(table, n16);

        const int gblocks = (B + 7) / 8;            // 8 warps/block, 1 row/warp
        gather_mean_f16_k32<<<gblocks, 256>>>(idx, out, B);
    } else {
        const float4* table = (const float4*)d_in[0];
        const int*    idx   = (const int*)d_in[1];
        float4*       out   = (float4*)d_out;
        const int blocks = (B + 7) / 8;
        gather_mean_generic<<<blocks, 256>>>(table, idx, out, B, K);
    }
}

// round 17
// speedup vs baseline: 1.0801x; 1.0801x over previous
#include <cuda_runtime.h>
#include <cuda_fp16.h>
#include <cstdint>

// out[b, :] = (1/K) * sum_k table[idx[b,k], :],  V=200000 D=128 B=50000 K=32.
//
// Composition of the two best measured components:
//  - Convert (R15): 2 float4/thread (32B lane stride), evict_first reads,
//    evict_last 16B stores -> fp16 scratch L2-resident.  ~17.6us measured.
//  - Gather (R16): 256-thr CTAs, warp/row, LDG.64/lane, batch-4 full unroll,
//    depth-2 __hadd2 pre-reduction, regs 32.             ~27.1us measured.

static constexpr long long MAX_VD4 = 6400000;   // 200000*128/4 uint2 slots
__device__ uint2 g_tab16[MAX_VD4];              // fp16 table: 51.2 MB scratch

__device__ __forceinline__ unsigned long long make_policy_el() {
    unsigned long long pol;
    asm("createpolicy.fractional.L2::evict_last.b64 %0, 1.0;" : "=l"(pol));
    return pol;
}

// ---------------- pass 1: f32 -> f16 convert (streaming, R15 form) -------
__global__ __launch_bounds__(256) void convert_f32_to_f16(
    const float4* __restrict__ in, long long n8)   // n8 = pairs of float4
{
    long long i = (long long)blockIdx.x * blockDim.x + threadIdx.x;
    if (i >= n8) return;
    const unsigned long long pol = make_policy_el();

    float4 a = __ldcs(&in[2 * i]);
    float4 b = __ldcs(&in[2 * i + 1]);
    __half2 h0 = __floats2half2_rn(a.x, a.y);
    __half2 h1 = __floats2half2_rn(a.z, a.w);
    __half2 h2 = __floats2half2_rn(b.x, b.y);
    __half2 h3 = __floats2half2_rn(b.z, b.w);
    unsigned u0 = *reinterpret_cast<unsigned*>(&h0);
    unsigned u1 = *reinterpret_cast<unsigned*>(&h1);
    unsigned u2 = *reinterpret_cast<unsigned*>(&h2);
    unsigned u3 = *reinterpret_cast<unsigned*>(&h3);
    asm volatile("st.global.L2::cache_hint.v4.b32 [%0], {%1,%2,%3,%4}, %5;"
                 :: "l"(&g_tab16[2 * i]), "r"(u0), "r"(u1), "r"(u2), "r"(u3),
                    "l"(pol));
}

// ---------------- pass 2: fp16 gather (R16 form) ----------------
__device__ __forceinline__ uint2 ldg64_pol(const char* p, unsigned long long pol) {
    uint2 v;
    asm volatile("ld.global.nc.L2::cache_hint.v2.b32 {%0,%1}, [%2], %3;"
                 : "=r"(v.x), "=r"(v.y) : "l"(p), "l"(pol));
    return v;
}

__global__ __launch_bounds__(256) void gather_mean_f16_k32(
    const int* __restrict__ idx,
    float4* __restrict__ out,
    int B)
{
    const int warp = (blockIdx.x * blockDim.x + threadIdx.x) >> 5;
    const int lane = threadIdx.x & 31;
    if (warp >= B) return;

    const unsigned long long pol = make_policy_el();
    const char* tab = (const char*)g_tab16;     // byte base; offsets fit in u32

    // coalesced 128B streaming load of this row's 32 indices
    int my_idx = __ldcs(&idx[(long long)warp * 32 + lane]);

    const unsigned laneOfs = (unsigned)lane * 8u;

    float ax = 0.f, ay = 0.f, az = 0.f, aw = 0.f;

#pragma unroll
    for (int kb = 0; kb < 32; kb += 4) {
        uint2 v[4];
#pragma unroll
        for (int j = 0; j < 4; ++j) {
            int n = __shfl_sync(0xffffffffu, my_idx, kb + j);
            unsigned ofs = (unsigned)n * 256u + laneOfs;   // fp16 row = 256B
            v[j] = ldg64_pol(tab + ofs, pol);
        }
        // depth-2 fp16 pre-reduction: combine 4 rows before conversion
        __half2 p0 = __hadd2(*reinterpret_cast<__half2*>(&v[0].x),
                             *reinterpret_cast<__half2*>(&v[1].x));
        __half2 q0 = __hadd2(*reinterpret_cast<__half2*>(&v[2].x),
                             *reinterpret_cast<__half2*>(&v[3].x));
        __half2 p1 = __hadd2(*reinterpret_cast<__half2*>(&v[0].y),
                             *reinterpret_cast<__half2*>(&v[1].y));
        __half2 q1 = __hadd2(*reinterpret_cast<__half2*>(&v[2].y),
                             *reinterpret_cast<__half2*>(&v[3].y));
        __half2 s0 = __hadd2(p0, q0);
        __half2 s1 = __hadd2(p1, q1);
        float2 f0 = __half22float2(s0);
        float2 f1 = __half22float2(s1);
        ax += f0.x; ay += f0.y;
        az += f1.x; aw += f1.y;
    }

    const float inv = 1.0f / 32.0f;
    float4 r;
    r.x = ax * inv; r.y = ay * inv; r.z = az * inv; r.w = aw * inv;
    __stcs(&out[(long long)warp * 32 + lane], r);
}

// ---------------- fallback: f32 path (K != 32 or oversized table) --------
__global__ __launch_bounds__(256) void gather_mean_generic(
    const float4* __restrict__ table,
    const int* __restrict__ idx,
    float4* __restrict__ out,
    int B, int K)
{
    const int warp = (blockIdx.x * blockDim.x + threadIdx.x) >> 5;
    const int lane = threadIdx.x & 31;
    if (warp >= B) return;

    const int* row_idx = idx + (long long)warp * K;

    float4 acc = make_float4(0.f, 0.f, 0.f, 0.f);
    int k = 0;
    for (; k + 8 <= K; k += 8) {
        float4 v[8];
#pragma unroll
        for (int j = 0; j < 8; ++j) {
            int n = __ldg(&row_idx[k + j]);
            v[j] = __ldg(&table[(long long)n * 32 + lane]);
        }
#pragma unroll
        for (int j = 0; j < 8; ++j) {
            acc.x += v[j].x; acc.y += v[j].y;
            acc.z += v[j].z; acc.w += v[j].w;
        }
    }
    for (; k < K; ++k) {
        int n = row_idx[k];
        float4 v = __ldg(&table[(long long)n * 32 + lane]);
        acc.x += v.x; acc.y += v.y; acc.z += v.z; acc.w += v.w;
    }

    const float inv = 1.0f / (float)K;
    acc.x *= inv; acc.y *= inv; acc.z *= inv; acc.w *= inv;
    out[(long long)warp * 32 + lane] = acc;
}

extern "C" void kernel_launch(void* const* d_in, const int* in_sizes, int n_in,
                              void* d_out, int out_size)
{
    const int B = out_size / 128;                   // rows of output
    const int K = (B > 0) ? (in_sizes[1] / B) : 0;
    const long long VD = (long long)in_sizes[0];    // table element count

    if (K == 32 && VD % 8 == 0 && VD / 4 <= MAX_VD4 && (VD & 127) == 0) {
        const float4* table = (const float4*)d_in[0];
        const int*    idx   = (const int*)d_in[1];
        float4*       out   = (float4*)d_out;

        const long long n8 = VD / 8;                // 2 float4 per thread
        const int cblocks = (int)((n8 + 255) / 256);
        convert_f32_to_f16<<<cblocks, 256>>>(table, n8);

        const int gblocks = (B + 7) / 8;            // 8 warps/block, 1 row/warp
        gather_mean_f16_k32<<<gblocks, 256>>>(idx, out, B);
    } else {
        const float4* table = (const float4*)d_in[0];
        const int*    idx   = (const int*)d_in[1];
        float4*       out   = (float4*)d_out;
        const int blocks = (B + 7) / 8;
        gather_mean_generic<<<blocks, 256>>>(table, idx, out, B, K);
    }
}